// round 13
// baseline (speedup 1.0000x reference)
#include <cuda_runtime.h>
#include <cuda_fp16.h>
#include <cstdint>

// ---------------------------------------------------------------------------
// SimpleMaxViTBlock: LN1 -> per-token head-mixing attention -> +res
//                    -> LN2 -> FFN -> +res
// GEMMs: mma.sync m16n8k16 fp16, fp32 accum, ldmatrix fragments.
// R13: 256-thread CTAs (8 warps, 4Mx2N, warp 32x64) x 2 CTAs/SM = 16 warps/SM
// (ncu shows tensor pipe at 27% with 8 warps/SM -> latency-bound, not
// pipe-bound; legacy HMMA peak measured ~1024 MAC/cyc/SM).
// ---------------------------------------------------------------------------

constexpr int TOKENS = 65536;
constexpr int DIM    = 256;
constexpr int HEADS  = 8;
constexpr int HD     = 32;
constexpr int FFNDIM = 1024;

// Scratch (device globals: allocation-free rule)
__device__ __half g_xn  [ (size_t)TOKENS * DIM    ];
__device__ __half g_qkv [ (size_t)TOKENS * 3*DIM  ];
__device__ __half g_attn[ (size_t)TOKENS * DIM    ];
__device__ float  g_y   [ (size_t)TOKENS * DIM    ];
__device__ __half g_h   [ (size_t)TOKENS * FFNDIM ];
__device__ __half g_w   [ 786432 ];   // fp16-rounded weights

constexpr int W_QKV  = 0;
constexpr int W_PROJ = 196608;
constexpr int W_FFN1 = 262144;
constexpr int W_FFN2 = 524288;

// ===================== helpers ==============================================
__device__ __forceinline__ uint32_t smem_u32(const void* p) {
    uint32_t a;
    asm("{ .reg .u64 t; cvta.to.shared.u64 t, %1; cvt.u32.u64 %0, t; }"
        : "=r"(a) : "l"(p));
    return a;
}
__device__ __forceinline__ void cp_async16(uint32_t saddr, const void* gaddr) {
    asm volatile("cp.async.cg.shared.global [%0], [%1], 16;"
                 :: "r"(saddr), "l"(gaddr) : "memory");
}
__device__ __forceinline__ void cp_commit() {
    asm volatile("cp.async.commit_group;" ::: "memory");
}
template<int N>
__device__ __forceinline__ void cp_wait() {
    asm volatile("cp.async.wait_group %0;" :: "n"(N) : "memory");
}
__device__ __forceinline__ void ldm_x4(uint32_t& r0, uint32_t& r1,
                                       uint32_t& r2, uint32_t& r3, uint32_t addr) {
    asm volatile("ldmatrix.sync.aligned.m8n8.x4.shared.b16 {%0,%1,%2,%3}, [%4];"
                 : "=r"(r0), "=r"(r1), "=r"(r2), "=r"(r3) : "r"(addr));
}
__device__ __forceinline__ void mma_f16(
    float& d0, float& d1, float& d2, float& d3,
    uint32_t a0, uint32_t a1, uint32_t a2, uint32_t a3,
    uint32_t b0, uint32_t b1)
{
    asm volatile(
        "mma.sync.aligned.m16n8k16.row.col.f32.f16.f16.f32 "
        "{%0,%1,%2,%3}, {%4,%5,%6,%7}, {%8,%9}, {%0,%1,%2,%3};"
        : "+f"(d0), "+f"(d1), "+f"(d2), "+f"(d3)
        : "r"(a0), "r"(a1), "r"(a2), "r"(a3), "r"(b0), "r"(b1));
}

// ===================== fp16 mma.sync GEMM ===================================
// C[m,n] = epi( sum_k A[m,k]*B[n,k] + bias[n] [+res] )
// CTA 128x128, BK=32 halves, double-buffered cp.async, 8 warps (4Mx2N),
// warp tile 32x64, ldmatrix fragments, fp32 accum, 2 CTAs/SM (16 warps/SM).
// MODE: 0 = bias -> half out, 1 = bias+relu -> half out, 2 = bias+res -> f32
constexpr int TILE  = 128;
constexpr int BK    = 32;
constexpr int LDU   = 20;              // u32 per smem row (= 40 halves, 80B)
constexpr int SLABU = TILE * LDU;      // 2560 u32 per stage per matrix

template<int MODE, typename OutT>
__global__ void __launch_bounds__(256, 2) mma_gemm(
    const __half* __restrict__ A, const __half* __restrict__ B,
    const float* __restrict__ bias, const float* __restrict__ res,
    OutT* __restrict__ C, int K, int N)
{
    __shared__ __align__(16) uint32_t sm[4 * SLABU];   // 40960 B
    const uint32_t As_u = smem_u32(sm);                // [2][128][20]
    const uint32_t Bs_u = As_u + 2 * SLABU * 4;        // [2][128][20]

    const int tid  = threadIdx.x;
    const int wid  = tid >> 5;          // 0..7
    const int lane = tid & 31;
    const int gid  = lane >> 2;
    const int tg   = lane & 3;

    const int bm = blockIdx.y * TILE;
    const int bn = blockIdx.x * TILE;
    const int m_off = (wid >> 1) * 32;   // 0,32,64,96
    const int n_off = (wid & 1) * 64;    // 0,64

    const int lrow8 = lane & 7;
    const int a_row = (lrow8 + ((lane >> 3) & 1) * 8);
    const int a_kof = (lane >> 4) * 4;
    const int b_row = (lrow8 + ((lane >> 4) & 1) * 8);
    const int b_kof = ((lane >> 3) & 1) * 4;

    // cp.async mapping: 512 16B-transfers per matrix, 256 threads x 2 iters
    const int crow = tid >> 2;          // 0..63, +64 per it
    const int cc4  = (tid & 3) * 4;     // u32 offset within 16 u32 of row data

    float d[2][8][4];
#pragma unroll
    for (int mt = 0; mt < 2; mt++)
#pragma unroll
        for (int nt = 0; nt < 8; nt++)
#pragma unroll
            for (int j = 0; j < 4; j++) d[mt][nt][j] = 0.0f;

    const int C_CHUNKS = K / BK;

    {
#pragma unroll
        for (int it = 0; it < 2; it++) {
            int row = crow + it * 64;
            cp_async16(As_u + (uint32_t)(row * LDU + cc4) * 4,
                       A + (size_t)(bm + row) * K + cc4 * 2);
            cp_async16(Bs_u + (uint32_t)(row * LDU + cc4) * 4,
                       B + (size_t)(bn + row) * K + cc4 * 2);
        }
        cp_commit();
    }

    for (int c = 0; c < C_CHUNKS; c++) {
        const int buf = c & 1;
        if (c + 1 < C_CHUNKS) {
            const int nb  = (c + 1) & 1;
            const int k0g = (c + 1) * BK;
#pragma unroll
            for (int it = 0; it < 2; it++) {
                int row = crow + it * 64;
                cp_async16(As_u + (uint32_t)((nb * SLABU + row * LDU + cc4) * 4),
                           A + (size_t)(bm + row) * K + k0g + cc4 * 2);
                cp_async16(Bs_u + (uint32_t)((nb * SLABU + row * LDU + cc4) * 4),
                           B + (size_t)(bn + row) * K + k0g + cc4 * 2);
            }
            cp_commit();
            cp_wait<1>();
        } else {
            cp_wait<0>();
        }
        __syncthreads();

        const uint32_t Ab = As_u + (uint32_t)(buf * SLABU) * 4;
        const uint32_t Bb = Bs_u + (uint32_t)(buf * SLABU) * 4;

#pragma unroll
        for (int ks = 0; ks < 2; ks++) {
            const int ko = ks * 8;
            uint32_t a[2][4];
#pragma unroll
            for (int mt = 0; mt < 2; mt++) {
                uint32_t addr = Ab + (uint32_t)(
                    (m_off + mt * 16 + a_row) * LDU + ko + a_kof) * 4;
                ldm_x4(a[mt][0], a[mt][1], a[mt][2], a[mt][3], addr);
            }
            uint32_t b[8][2];
#pragma unroll
            for (int np = 0; np < 4; np++) {
                uint32_t addr = Bb + (uint32_t)(
                    (n_off + np * 16 + b_row) * LDU + ko + b_kof) * 4;
                ldm_x4(b[2*np][0], b[2*np][1], b[2*np+1][0], b[2*np+1][1], addr);
            }
#pragma unroll
            for (int mt = 0; mt < 2; mt++)
#pragma unroll
                for (int nt = 0; nt < 8; nt++)
                    mma_f16(d[mt][nt][0], d[mt][nt][1], d[mt][nt][2], d[mt][nt][3],
                            a[mt][0], a[mt][1], a[mt][2], a[mt][3],
                            b[nt][0], b[nt][1]);
        }
        __syncthreads();
    }

#pragma unroll
    for (int nt = 0; nt < 8; nt++) {
        const int n = bn + n_off + nt * 8 + 2 * tg;
        const float2 bv = *(const float2*)&bias[n];
#pragma unroll
        for (int mt = 0; mt < 2; mt++) {
            const int m0 = bm + m_off + mt * 16 + gid;
#pragma unroll
            for (int half_i = 0; half_i < 2; half_i++) {
                const int m = m0 + half_i * 8;
                float vx = d[mt][nt][half_i * 2 + 0] + bv.x;
                float vy = d[mt][nt][half_i * 2 + 1] + bv.y;
                if (MODE == 1) { vx = fmaxf(vx, 0.f); vy = fmaxf(vy, 0.f); }
                if (MODE == 2) {
                    const float2 r = *(const float2*)&res[(size_t)m * N + n];
                    float2 v; v.x = vx + r.x; v.y = vy + r.y;
                    *(float2*)&((float*)C)[(size_t)m * N + n] = v;
                } else {
                    *(__half2*)&((__half*)C)[(size_t)m * N + n] =
                        __floats2half2_rn(vx, vy);
                }
            }
        }
    }
}

// ===================== LayerNorm row helper =================================
__device__ __forceinline__ void ln_row(
    const float* __restrict__ x, const float* __restrict__ g,
    const float* __restrict__ b, __half* __restrict__ out,
    int row, int lane)
{
    const float4* xr = (const float4*)(x + (size_t)row * DIM);
    float4 v0 = xr[lane];
    float4 v1 = xr[lane + 32];

    float s = v0.x + v0.y + v0.z + v0.w + v1.x + v1.y + v1.z + v1.w;
    float q = v0.x*v0.x + v0.y*v0.y + v0.z*v0.z + v0.w*v0.w
            + v1.x*v1.x + v1.y*v1.y + v1.z*v1.z + v1.w*v1.w;
#pragma unroll
    for (int o = 16; o > 0; o >>= 1) {
        s += __shfl_xor_sync(0xffffffffu, s, o);
        q += __shfl_xor_sync(0xffffffffu, q, o);
    }
    float mean = s * (1.0f / 256.0f);
    float var  = q * (1.0f / 256.0f) - mean * mean;
    float inv  = rsqrtf(var + 1e-5f);

    const float4* g4 = (const float4*)g;
    const float4* b4 = (const float4*)b;
    float4 ga = g4[lane], gb = g4[lane + 32];
    float4 ba = b4[lane], bb = b4[lane + 32];

    __half2 h0 = __floats2half2_rn((v0.x - mean) * inv * ga.x + ba.x,
                                   (v0.y - mean) * inv * ga.y + ba.y);
    __half2 h1 = __floats2half2_rn((v0.z - mean) * inv * ga.z + ba.z,
                                   (v0.w - mean) * inv * ga.w + ba.w);
    __half2 h2 = __floats2half2_rn((v1.x - mean) * inv * gb.x + bb.x,
                                   (v1.y - mean) * inv * gb.y + bb.y);
    __half2 h3 = __floats2half2_rn((v1.z - mean) * inv * gb.z + bb.z,
                                   (v1.w - mean) * inv * gb.w + bb.w);

    __half* orow = out + (size_t)row * DIM;
    uint2 p0; p0.x = *(uint32_t*)&h0; p0.y = *(uint32_t*)&h1;
    uint2 p1; p1.x = *(uint32_t*)&h2; p1.y = *(uint32_t*)&h3;
    *(uint2*)(orow + lane * 4)       = p0;
    *(uint2*)(orow + 128 + lane * 4) = p1;
}

// ===================== init: weight rounding + LN1, one launch ==============
__global__ void __launch_bounds__(256) init_kernel(
    const float* __restrict__ qkv_w, const float* __restrict__ proj_w,
    const float* __restrict__ ffn_w1, const float* __restrict__ ffn_w2,
    __half* __restrict__ wdst,
    const float* __restrict__ x, const float* __restrict__ ln1g,
    const float* __restrict__ ln1b, __half* __restrict__ xn)
{
    if (blockIdx.x < 768) {
        int i = blockIdx.x * 256 + threadIdx.x;      // float4 index
        const float* src;
        int local;
        if (i < 49152)       { src = qkv_w;  local = i;           }
        else if (i < 65536)  { src = proj_w; local = i - 49152;   }
        else if (i < 131072) { src = ffn_w1; local = i - 65536;   }
        else                 { src = ffn_w2; local = i - 131072;  }
        float4 v = ((const float4*)src)[local];
        __half2 lo = __floats2half2_rn(v.x, v.y);
        __half2 hi = __floats2half2_rn(v.z, v.w);
        uint2 o; o.x = *(uint32_t*)&lo; o.y = *(uint32_t*)&hi;
        ((uint2*)wdst)[i] = o;
    } else {
        int row = ((blockIdx.x - 768) * 256 + threadIdx.x) >> 5;
        ln_row(x, ln1g, ln1b, xn, row, threadIdx.x & 31);
    }
}

// ===================== LayerNorm (LN2) ======================================
__global__ void __launch_bounds__(256) ln_kernel(
    const float* __restrict__ x, const float* __restrict__ g,
    const float* __restrict__ b, __half* __restrict__ out)
{
    int row  = (blockIdx.x * blockDim.x + threadIdx.x) >> 5;
    ln_row(x, g, b, out, row, threadIdx.x & 31);
}

// ===================== Per-token head-mixing attention ======================
__global__ void __launch_bounds__(256) attn_kernel(
    const __half* __restrict__ qkv, __half* __restrict__ out)
{
    const int idx = blockIdx.x * 256 + threadIdx.x;  // (token, head)
    const int t = idx >> 3;
    const int h = idx & 7;
    const __half* base = qkv + (size_t)t * 768;

    float q[HD];
#pragma unroll
    for (int c4 = 0; c4 < 4; c4++) {
        uint4 qv = *(const uint4*)(base + h * HD + c4 * 8);
        const __half2* qh = (const __half2*)&qv;
#pragma unroll
        for (int j = 0; j < 4; j++) {
            float2 f = __half22float2(qh[j]);
            q[c4 * 8 + 2*j] = f.x; q[c4 * 8 + 2*j + 1] = f.y;
        }
    }

    const float scale = 0.17677669529663688f;   // 1/sqrt(32)
    float sc[HEADS];
    float mx = -1e30f;
#pragma unroll
    for (int g = 0; g < HEADS; g++) {
        float s = 0.0f;
#pragma unroll
        for (int c4 = 0; c4 < 4; c4++) {
            uint4 kv = *(const uint4*)(base + 256 + g * HD + c4 * 8);
            const __half2* kh = (const __half2*)&kv;
#pragma unroll
            for (int j = 0; j < 4; j++) {
                float2 f = __half22float2(kh[j]);
                s += q[c4 * 8 + 2*j] * f.x + q[c4 * 8 + 2*j + 1] * f.y;
            }
        }
        s *= scale;
        sc[g] = s;
        mx = fmaxf(mx, s);
    }
    float sum = 0.0f;
#pragma unroll
    for (int g = 0; g < HEADS; g++) {
        float e = __expf(sc[g] - mx);
        sc[g] = e;
        sum += e;
    }
    const float inv = 1.0f / sum;

    float acc[HD];
#pragma unroll
    for (int d0 = 0; d0 < HD; d0++) acc[d0] = 0.0f;
#pragma unroll
    for (int g = 0; g < HEADS; g++) {
        const float p = sc[g];
#pragma unroll
        for (int c4 = 0; c4 < 4; c4++) {
            uint4 vv = *(const uint4*)(base + 512 + g * HD + c4 * 8);
            const __half2* vh = (const __half2*)&vv;
#pragma unroll
            for (int j = 0; j < 4; j++) {
                float2 f = __half22float2(vh[j]);
                acc[c4 * 8 + 2*j]     += p * f.x;
                acc[c4 * 8 + 2*j + 1] += p * f.y;
            }
        }
    }

    __half* orow = out + (size_t)t * DIM + h * HD;
#pragma unroll
    for (int c4 = 0; c4 < 4; c4++) {
        __half2 o0 = __floats2half2_rn(acc[c4*8+0] * inv, acc[c4*8+1] * inv);
        __half2 o1 = __floats2half2_rn(acc[c4*8+2] * inv, acc[c4*8+3] * inv);
        __half2 o2 = __floats2half2_rn(acc[c4*8+4] * inv, acc[c4*8+5] * inv);
        __half2 o3 = __floats2half2_rn(acc[c4*8+6] * inv, acc[c4*8+7] * inv);
        uint4 p;
        p.x = *(uint32_t*)&o0; p.y = *(uint32_t*)&o1;
        p.z = *(uint32_t*)&o2; p.w = *(uint32_t*)&o3;
        *(uint4*)(orow + c4 * 8) = p;
    }
}

// ===================== Launch ===============================================
extern "C" void kernel_launch(void* const* d_in, const int* in_sizes, int n_in,
                              void* d_out, int out_size)
{
    const float* x      = (const float*)d_in[0];
    const float* ln1_g  = (const float*)d_in[1];
    const float* ln1_b  = (const float*)d_in[2];
    const float* qkv_w  = (const float*)d_in[3];
    const float* qkv_b  = (const float*)d_in[4];
    const float* proj_w = (const float*)d_in[5];
    const float* proj_b = (const float*)d_in[6];
    const float* ln2_g  = (const float*)d_in[7];
    const float* ln2_b  = (const float*)d_in[8];
    const float* ffn_w1 = (const float*)d_in[9];
    const float* ffn_b1 = (const float*)d_in[10];
    const float* ffn_w2 = (const float*)d_in[11];
    const float* ffn_b2 = (const float*)d_in[12];

    __half *xn, *qkv, *attn, *h, *w;
    float  *y;
    cudaGetSymbolAddress((void**)&xn,   g_xn);
    cudaGetSymbolAddress((void**)&qkv,  g_qkv);
    cudaGetSymbolAddress((void**)&attn, g_attn);
    cudaGetSymbolAddress((void**)&y,    g_y);
    cudaGetSymbolAddress((void**)&h,    g_h);
    cudaGetSymbolAddress((void**)&w,    g_w);
    float* out = (float*)d_out;

    const int MROWS = TOKENS / TILE;   // 512

    // 0+1) weight rounding + LN1 in one launch
    init_kernel<<<768 + TOKENS / 8, 256>>>(
        qkv_w, proj_w, ffn_w1, ffn_w2, w, x, ln1_g, ln1_b, xn);
    // 2) QKV = xn @ qkv_w^T + qkv_b          [65536, 768] half
    mma_gemm<0, __half><<<dim3(768 / TILE, MROWS), 256>>>(
        xn, w + W_QKV, qkv_b, nullptr, qkv, DIM, 3 * DIM);
    // 3) per-token head-mixing attention (half out)
    attn_kernel<<<TOKENS * 8 / 256, 256>>>(qkv, attn);
    // 4) y = x + attn @ proj_w^T + proj_b    [65536, 256] f32
    mma_gemm<2, float><<<dim3(DIM / TILE, MROWS), 256>>>(
        attn, w + W_PROJ, proj_b, x, y, DIM, DIM);
    // 5) LN2 (half out)
    ln_kernel<<<TOKENS / 8, 256>>>(y, ln2_g, ln2_b, xn);
    // 6) h = relu(xn @ ffn_w1^T + ffn_b1)    [65536, 1024] half
    mma_gemm<1, __half><<<dim3(FFNDIM / TILE, MROWS), 256>>>(
        xn, w + W_FFN1, ffn_b1, nullptr, h, DIM, FFNDIM);
    // 7) out = y + h @ ffn_w2^T + ffn_b2     [65536, 256] f32
    mma_gemm<2, float><<<dim3(DIM / TILE, MROWS), 256>>>(
        h, w + W_FFN2, ffn_b2, y, out, FFNDIM, DIM);
}

// round 14
// speedup vs baseline: 1.0366x; 1.0366x over previous
#include <cuda_runtime.h>
#include <cuda_fp16.h>
#include <cstdint>

// ---------------------------------------------------------------------------
// SimpleMaxViTBlock: LN1 -> per-token head-mixing attention -> +res
//                    -> LN2 -> FFN -> +res
// GEMMs: mma.sync m16n8k16 fp16, fp32 accum, ldmatrix, 4 warps (2x2) 64x64,
// double-buffered cp.async, 2 CTAs/SM (R8 config - best measured).
// R14: y residual stored fp16 (-96 MB DRAM traffic; graph is bytes-bound).
// ---------------------------------------------------------------------------

constexpr int TOKENS = 65536;
constexpr int DIM    = 256;
constexpr int HEADS  = 8;
constexpr int HD     = 32;
constexpr int FFNDIM = 1024;

// Scratch (device globals: allocation-free rule)
__device__ __half g_xn  [ (size_t)TOKENS * DIM    ];
__device__ __half g_qkv [ (size_t)TOKENS * 3*DIM  ];
__device__ __half g_attn[ (size_t)TOKENS * DIM    ];
__device__ __half g_y   [ (size_t)TOKENS * DIM    ];   // fp16 residual
__device__ __half g_h   [ (size_t)TOKENS * FFNDIM ];
__device__ __half g_w   [ 786432 ];   // fp16-rounded weights

constexpr int W_QKV  = 0;
constexpr int W_PROJ = 196608;
constexpr int W_FFN1 = 262144;
constexpr int W_FFN2 = 524288;

// ===================== helpers ==============================================
__device__ __forceinline__ uint32_t smem_u32(const void* p) {
    uint32_t a;
    asm("{ .reg .u64 t; cvta.to.shared.u64 t, %1; cvt.u32.u64 %0, t; }"
        : "=r"(a) : "l"(p));
    return a;
}
__device__ __forceinline__ void cp_async16(uint32_t saddr, const void* gaddr) {
    asm volatile("cp.async.cg.shared.global [%0], [%1], 16;"
                 :: "r"(saddr), "l"(gaddr) : "memory");
}
__device__ __forceinline__ void cp_commit() {
    asm volatile("cp.async.commit_group;" ::: "memory");
}
template<int N>
__device__ __forceinline__ void cp_wait() {
    asm volatile("cp.async.wait_group %0;" :: "n"(N) : "memory");
}
__device__ __forceinline__ void ldm_x4(uint32_t& r0, uint32_t& r1,
                                       uint32_t& r2, uint32_t& r3, uint32_t addr) {
    asm volatile("ldmatrix.sync.aligned.m8n8.x4.shared.b16 {%0,%1,%2,%3}, [%4];"
                 : "=r"(r0), "=r"(r1), "=r"(r2), "=r"(r3) : "r"(addr));
}
__device__ __forceinline__ void mma_f16(
    float& d0, float& d1, float& d2, float& d3,
    uint32_t a0, uint32_t a1, uint32_t a2, uint32_t a3,
    uint32_t b0, uint32_t b1)
{
    asm volatile(
        "mma.sync.aligned.m16n8k16.row.col.f32.f16.f16.f32 "
        "{%0,%1,%2,%3}, {%4,%5,%6,%7}, {%8,%9}, {%0,%1,%2,%3};"
        : "+f"(d0), "+f"(d1), "+f"(d2), "+f"(d3)
        : "r"(a0), "r"(a1), "r"(a2), "r"(a3), "r"(b0), "r"(b1));
}

// ===================== fp16 mma.sync GEMM (R8 config) =======================
// C[m,n] = epi( sum_k A[m,k]*B[n,k] + bias[n] [+res] )
// CTA 128x128, BK=32 halves, double-buffered cp.async, 4 warps (2x2),
// warp tile 64x64, ldmatrix frags, fp32 accum, 2 CTAs/SM.
// MODE: 0 = bias, 1 = bias+relu, 2 = bias+residual(ResT)
constexpr int TILE  = 128;
constexpr int BK    = 32;
constexpr int LDU   = 20;              // u32 per smem row (= 40 halves, 80B)
constexpr int SLABU = TILE * LDU;      // 2560 u32 per stage per matrix

template<int MODE, typename ResT, typename OutT>
__global__ void __launch_bounds__(128, 2) mma_gemm(
    const __half* __restrict__ A, const __half* __restrict__ B,
    const float* __restrict__ bias, const ResT* __restrict__ res,
    OutT* __restrict__ C, int K, int N)
{
    __shared__ __align__(16) uint32_t sm[4 * SLABU];   // 40960 B
    const uint32_t As_u = smem_u32(sm);
    const uint32_t Bs_u = As_u + 2 * SLABU * 4;

    const int tid  = threadIdx.x;
    const int wid  = tid >> 5;
    const int lane = tid & 31;
    const int gid  = lane >> 2;
    const int tg   = lane & 3;

    const int bm = blockIdx.y * TILE;
    const int bn = blockIdx.x * TILE;
    const int m_off = (wid >> 1) * 64;
    const int n_off = (wid & 1) * 64;

    const int lrow8 = lane & 7;
    const int a_row = (lrow8 + ((lane >> 3) & 1) * 8);
    const int a_kof = (lane >> 4) * 4;
    const int b_row = (lrow8 + ((lane >> 4) & 1) * 8);
    const int b_kof = ((lane >> 3) & 1) * 4;

    const int crow = tid >> 2;
    const int cc4  = (tid & 3) * 4;

    float d[4][8][4];
#pragma unroll
    for (int mt = 0; mt < 4; mt++)
#pragma unroll
        for (int nt = 0; nt < 8; nt++)
#pragma unroll
            for (int j = 0; j < 4; j++) d[mt][nt][j] = 0.0f;

    const int C_CHUNKS = K / BK;

    {
#pragma unroll
        for (int it = 0; it < 4; it++) {
            int row = crow + it * 32;
            cp_async16(As_u + (uint32_t)(row * LDU + cc4) * 4,
                       A + (size_t)(bm + row) * K + cc4 * 2);
            cp_async16(Bs_u + (uint32_t)(row * LDU + cc4) * 4,
                       B + (size_t)(bn + row) * K + cc4 * 2);
        }
        cp_commit();
    }

    for (int c = 0; c < C_CHUNKS; c++) {
        const int buf = c & 1;
        if (c + 1 < C_CHUNKS) {
            const int nb  = (c + 1) & 1;
            const int k0g = (c + 1) * BK;
#pragma unroll
            for (int it = 0; it < 4; it++) {
                int row = crow + it * 32;
                cp_async16(As_u + (uint32_t)((nb * SLABU + row * LDU + cc4) * 4),
                           A + (size_t)(bm + row) * K + k0g + cc4 * 2);
                cp_async16(Bs_u + (uint32_t)((nb * SLABU + row * LDU + cc4) * 4),
                           B + (size_t)(bn + row) * K + k0g + cc4 * 2);
            }
            cp_commit();
            cp_wait<1>();
        } else {
            cp_wait<0>();
        }
        __syncthreads();

        const uint32_t Ab = As_u + (uint32_t)(buf * SLABU) * 4;
        const uint32_t Bb = Bs_u + (uint32_t)(buf * SLABU) * 4;

#pragma unroll
        for (int ks = 0; ks < 2; ks++) {
            const int ko = ks * 8;
            uint32_t a[4][4];
#pragma unroll
            for (int mt = 0; mt < 4; mt++) {
                uint32_t addr = Ab + (uint32_t)(
                    (m_off + mt * 16 + a_row) * LDU + ko + a_kof) * 4;
                ldm_x4(a[mt][0], a[mt][1], a[mt][2], a[mt][3], addr);
            }
            uint32_t b[8][2];
#pragma unroll
            for (int np = 0; np < 4; np++) {
                uint32_t addr = Bb + (uint32_t)(
                    (n_off + np * 16 + b_row) * LDU + ko + b_kof) * 4;
                ldm_x4(b[2*np][0], b[2*np][1], b[2*np+1][0], b[2*np+1][1], addr);
            }
#pragma unroll
            for (int mt = 0; mt < 4; mt++)
#pragma unroll
                for (int nt = 0; nt < 8; nt++)
                    mma_f16(d[mt][nt][0], d[mt][nt][1], d[mt][nt][2], d[mt][nt][3],
                            a[mt][0], a[mt][1], a[mt][2], a[mt][3],
                            b[nt][0], b[nt][1]);
        }
        __syncthreads();
    }

#pragma unroll
    for (int nt = 0; nt < 8; nt++) {
        const int n = bn + n_off + nt * 8 + 2 * tg;
        const float2 bv = *(const float2*)&bias[n];
#pragma unroll
        for (int mt = 0; mt < 4; mt++) {
            const int m0 = bm + m_off + mt * 16 + gid;
#pragma unroll
            for (int half_i = 0; half_i < 2; half_i++) {
                const int m = m0 + half_i * 8;
                float vx = d[mt][nt][half_i * 2 + 0] + bv.x;
                float vy = d[mt][nt][half_i * 2 + 1] + bv.y;
                if (MODE == 1) { vx = fmaxf(vx, 0.f); vy = fmaxf(vy, 0.f); }
                if (MODE == 2) {
                    if constexpr (sizeof(ResT) == 4) {
                        const float2 r = *(const float2*)&res[(size_t)m * N + n];
                        vx += r.x; vy += r.y;
                    } else {
                        const __half2 r = *(const __half2*)&res[(size_t)m * N + n];
                        float2 rf = __half22float2(r);
                        vx += rf.x; vy += rf.y;
                    }
                }
                if constexpr (sizeof(OutT) == 4) {
                    float2 v; v.x = vx; v.y = vy;
                    *(float2*)&((float*)C)[(size_t)m * N + n] = v;
                } else {
                    *(__half2*)&((__half*)C)[(size_t)m * N + n] =
                        __floats2half2_rn(vx, vy);
                }
            }
        }
    }
}

// ===================== LayerNorm row helpers ================================
__device__ __forceinline__ void ln_row_f32(
    const float* __restrict__ x, const float* __restrict__ g,
    const float* __restrict__ b, __half* __restrict__ out,
    int row, int lane)
{
    const float4* xr = (const float4*)(x + (size_t)row * DIM);
    float4 v0 = xr[lane];
    float4 v1 = xr[lane + 32];

    float s = v0.x + v0.y + v0.z + v0.w + v1.x + v1.y + v1.z + v1.w;
    float q = v0.x*v0.x + v0.y*v0.y + v0.z*v0.z + v0.w*v0.w
            + v1.x*v1.x + v1.y*v1.y + v1.z*v1.z + v1.w*v1.w;
#pragma unroll
    for (int o = 16; o > 0; o >>= 1) {
        s += __shfl_xor_sync(0xffffffffu, s, o);
        q += __shfl_xor_sync(0xffffffffu, q, o);
    }
    float mean = s * (1.0f / 256.0f);
    float var  = q * (1.0f / 256.0f) - mean * mean;
    float inv  = rsqrtf(var + 1e-5f);

    const float4* g4 = (const float4*)g;
    const float4* b4 = (const float4*)b;
    float4 ga = g4[lane], gb = g4[lane + 32];
    float4 ba = b4[lane], bb = b4[lane + 32];

    __half2 h0 = __floats2half2_rn((v0.x - mean) * inv * ga.x + ba.x,
                                   (v0.y - mean) * inv * ga.y + ba.y);
    __half2 h1 = __floats2half2_rn((v0.z - mean) * inv * ga.z + ba.z,
                                   (v0.w - mean) * inv * ga.w + ba.w);
    __half2 h2 = __floats2half2_rn((v1.x - mean) * inv * gb.x + bb.x,
                                   (v1.y - mean) * inv * gb.y + bb.y);
    __half2 h3 = __floats2half2_rn((v1.z - mean) * inv * gb.z + bb.z,
                                   (v1.w - mean) * inv * gb.w + bb.w);

    __half* orow = out + (size_t)row * DIM;
    uint2 p0; p0.x = *(uint32_t*)&h0; p0.y = *(uint32_t*)&h1;
    uint2 p1; p1.x = *(uint32_t*)&h2; p1.y = *(uint32_t*)&h3;
    *(uint2*)(orow + lane * 4)       = p0;
    *(uint2*)(orow + 128 + lane * 4) = p1;
}

// half input variant: lane owns cols [lane*8, lane*8+8)
__device__ __forceinline__ void ln_row_f16(
    const __half* __restrict__ y, const float* __restrict__ g,
    const float* __restrict__ b, __half* __restrict__ out,
    int row, int lane)
{
    uint4 v = *(const uint4*)(y + (size_t)row * DIM + lane * 8);
    const __half2* vh = (const __half2*)&v;
    float f[8];
#pragma unroll
    for (int j = 0; j < 4; j++) {
        float2 ff = __half22float2(vh[j]);
        f[2*j] = ff.x; f[2*j + 1] = ff.y;
    }

    float s = 0.f, q = 0.f;
#pragma unroll
    for (int j = 0; j < 8; j++) { s += f[j]; q += f[j] * f[j]; }
#pragma unroll
    for (int o = 16; o > 0; o >>= 1) {
        s += __shfl_xor_sync(0xffffffffu, s, o);
        q += __shfl_xor_sync(0xffffffffu, q, o);
    }
    float mean = s * (1.0f / 256.0f);
    float var  = q * (1.0f / 256.0f) - mean * mean;
    float inv  = rsqrtf(var + 1e-5f);

    float4 ga = ((const float4*)g)[lane * 2];
    float4 gb = ((const float4*)g)[lane * 2 + 1];
    float4 ba = ((const float4*)b)[lane * 2];
    float4 bb = ((const float4*)b)[lane * 2 + 1];

    __half2 h0 = __floats2half2_rn((f[0] - mean) * inv * ga.x + ba.x,
                                   (f[1] - mean) * inv * ga.y + ba.y);
    __half2 h1 = __floats2half2_rn((f[2] - mean) * inv * ga.z + ba.z,
                                   (f[3] - mean) * inv * ga.w + ba.w);
    __half2 h2 = __floats2half2_rn((f[4] - mean) * inv * gb.x + bb.x,
                                   (f[5] - mean) * inv * gb.y + bb.y);
    __half2 h3 = __floats2half2_rn((f[6] - mean) * inv * gb.z + bb.z,
                                   (f[7] - mean) * inv * gb.w + bb.w);

    uint4 p;
    p.x = *(uint32_t*)&h0; p.y = *(uint32_t*)&h1;
    p.z = *(uint32_t*)&h2; p.w = *(uint32_t*)&h3;
    *(uint4*)(out + (size_t)row * DIM + lane * 8) = p;
}

// ===================== init: weight rounding + LN1, one launch ==============
__global__ void __launch_bounds__(256) init_kernel(
    const float* __restrict__ qkv_w, const float* __restrict__ proj_w,
    const float* __restrict__ ffn_w1, const float* __restrict__ ffn_w2,
    __half* __restrict__ wdst,
    const float* __restrict__ x, const float* __restrict__ ln1g,
    const float* __restrict__ ln1b, __half* __restrict__ xn)
{
    if (blockIdx.x < 768) {
        int i = blockIdx.x * 256 + threadIdx.x;      // float4 index
        const float* src;
        int local;
        if (i < 49152)       { src = qkv_w;  local = i;           }
        else if (i < 65536)  { src = proj_w; local = i - 49152;   }
        else if (i < 131072) { src = ffn_w1; local = i - 65536;   }
        else                 { src = ffn_w2; local = i - 131072;  }
        float4 v = ((const float4*)src)[local];
        __half2 lo = __floats2half2_rn(v.x, v.y);
        __half2 hi = __floats2half2_rn(v.z, v.w);
        uint2 o; o.x = *(uint32_t*)&lo; o.y = *(uint32_t*)&hi;
        ((uint2*)wdst)[i] = o;
    } else {
        int row = ((blockIdx.x - 768) * 256 + threadIdx.x) >> 5;
        ln_row_f32(x, ln1g, ln1b, xn, row, threadIdx.x & 31);
    }
}

// ===================== LayerNorm (LN2, half in/out) =========================
__global__ void __launch_bounds__(256) ln2_kernel(
    const __half* __restrict__ y, const float* __restrict__ g,
    const float* __restrict__ b, __half* __restrict__ out)
{
    int row = (blockIdx.x * blockDim.x + threadIdx.x) >> 5;
    ln_row_f16(y, g, b, out, row, threadIdx.x & 31);
}

// ===================== Per-token head-mixing attention ======================
__global__ void __launch_bounds__(256) attn_kernel(
    const __half* __restrict__ qkv, __half* __restrict__ out)
{
    const int idx = blockIdx.x * 256 + threadIdx.x;  // (token, head)
    const int t = idx >> 3;
    const int h = idx & 7;
    const __half* base = qkv + (size_t)t * 768;

    float q[HD];
#pragma unroll
    for (int c4 = 0; c4 < 4; c4++) {
        uint4 qv = *(const uint4*)(base + h * HD + c4 * 8);
        const __half2* qh = (const __half2*)&qv;
#pragma unroll
        for (int j = 0; j < 4; j++) {
            float2 f = __half22float2(qh[j]);
            q[c4 * 8 + 2*j] = f.x; q[c4 * 8 + 2*j + 1] = f.y;
        }
    }

    const float scale = 0.17677669529663688f;   // 1/sqrt(32)
    float sc[HEADS];
    float mx = -1e30f;
#pragma unroll
    for (int g = 0; g < HEADS; g++) {
        float s = 0.0f;
#pragma unroll
        for (int c4 = 0; c4 < 4; c4++) {
            uint4 kv = *(const uint4*)(base + 256 + g * HD + c4 * 8);
            const __half2* kh = (const __half2*)&kv;
#pragma unroll
            for (int j = 0; j < 4; j++) {
                float2 f = __half22float2(kh[j]);
                s += q[c4 * 8 + 2*j] * f.x + q[c4 * 8 + 2*j + 1] * f.y;
            }
        }
        s *= scale;
        sc[g] = s;
        mx = fmaxf(mx, s);
    }
    float sum = 0.0f;
#pragma unroll
    for (int g = 0; g < HEADS; g++) {
        float e = __expf(sc[g] - mx);
        sc[g] = e;
        sum += e;
    }
    const float inv = 1.0f / sum;

    float acc[HD];
#pragma unroll
    for (int d0 = 0; d0 < HD; d0++) acc[d0] = 0.0f;
#pragma unroll
    for (int g = 0; g < HEADS; g++) {
        const float p = sc[g];
#pragma unroll
        for (int c4 = 0; c4 < 4; c4++) {
            uint4 vv = *(const uint4*)(base + 512 + g * HD + c4 * 8);
            const __half2* vh = (const __half2*)&vv;
#pragma unroll
            for (int j = 0; j < 4; j++) {
                float2 f = __half22float2(vh[j]);
                acc[c4 * 8 + 2*j]     += p * f.x;
                acc[c4 * 8 + 2*j + 1] += p * f.y;
            }
        }
    }

    __half* orow = out + (size_t)t * DIM + h * HD;
#pragma unroll
    for (int c4 = 0; c4 < 4; c4++) {
        __half2 o0 = __floats2half2_rn(acc[c4*8+0] * inv, acc[c4*8+1] * inv);
        __half2 o1 = __floats2half2_rn(acc[c4*8+2] * inv, acc[c4*8+3] * inv);
        __half2 o2 = __floats2half2_rn(acc[c4*8+4] * inv, acc[c4*8+5] * inv);
        __half2 o3 = __floats2half2_rn(acc[c4*8+6] * inv, acc[c4*8+7] * inv);
        uint4 p;
        p.x = *(uint32_t*)&o0; p.y = *(uint32_t*)&o1;
        p.z = *(uint32_t*)&o2; p.w = *(uint32_t*)&o3;
        *(uint4*)(orow + c4 * 8) = p;
    }
}

// ===================== Launch ===============================================
extern "C" void kernel_launch(void* const* d_in, const int* in_sizes, int n_in,
                              void* d_out, int out_size)
{
    const float* x      = (const float*)d_in[0];
    const float* ln1_g  = (const float*)d_in[1];
    const float* ln1_b  = (const float*)d_in[2];
    const float* qkv_w  = (const float*)d_in[3];
    const float* qkv_b  = (const float*)d_in[4];
    const float* proj_w = (const float*)d_in[5];
    const float* proj_b = (const float*)d_in[6];
    const float* ln2_g  = (const float*)d_in[7];
    const float* ln2_b  = (const float*)d_in[8];
    const float* ffn_w1 = (const float*)d_in[9];
    const float* ffn_b1 = (const float*)d_in[10];
    const float* ffn_w2 = (const float*)d_in[11];
    const float* ffn_b2 = (const float*)d_in[12];

    __half *xn, *qkv, *attn, *y, *h, *w;
    cudaGetSymbolAddress((void**)&xn,   g_xn);
    cudaGetSymbolAddress((void**)&qkv,  g_qkv);
    cudaGetSymbolAddress((void**)&attn, g_attn);
    cudaGetSymbolAddress((void**)&y,    g_y);
    cudaGetSymbolAddress((void**)&h,    g_h);
    cudaGetSymbolAddress((void**)&w,    g_w);
    float* out = (float*)d_out;

    const int MROWS = TOKENS / TILE;   // 512

    // 0+1) weight rounding + LN1 in one launch
    init_kernel<<<768 + TOKENS / 8, 256>>>(
        qkv_w, proj_w, ffn_w1, ffn_w2, w, x, ln1_g, ln1_b, xn);
    // 2) QKV = xn @ qkv_w^T + qkv_b          [65536, 768] half
    mma_gemm<0, float, __half><<<dim3(768 / TILE, MROWS), 128>>>(
        xn, w + W_QKV, qkv_b, nullptr, qkv, DIM, 3 * DIM);
    // 3) per-token head-mixing attention (half out)
    attn_kernel<<<TOKENS * 8 / 256, 256>>>(qkv, attn);
    // 4) y = x + attn @ proj_w^T + proj_b    [65536, 256] half (res = x f32)
    mma_gemm<2, float, __half><<<dim3(DIM / TILE, MROWS), 128>>>(
        attn, w + W_PROJ, proj_b, x, y, DIM, DIM);
    // 5) LN2 (half in, half out)
    ln2_kernel<<<TOKENS / 8, 256>>>(y, ln2_g, ln2_b, xn);
    // 6) h = relu(xn @ ffn_w1^T + ffn_b1)    [65536, 1024] half
    mma_gemm<1, float, __half><<<dim3(FFNDIM / TILE, MROWS), 128>>>(
        xn, w + W_FFN1, ffn_b1, nullptr, h, DIM, FFNDIM);
    // 7) out = y + h @ ffn_w2^T + ffn_b2     [65536, 256] f32 (res = y half)
    mma_gemm<2, __half, float><<<dim3(DIM / TILE, MROWS), 128>>>(
        h, w + W_FFN2, ffn_b2, y, out, FFNDIM, DIM);
}